// round 10
// baseline (speedup 1.0000x reference)
#include <cuda_runtime.h>

// ---------------------------------------------------------------------------
// LTFGW on GB300 (sm_103a).
//   k1_dots: register-tiled GEMM. x cached transposed [e][node] (stride 36,
//   float4 loads -> xst MUST be 16B-aligned; R9 fix: alignas(16). R8's trap
//   was xst landing at offset 25800 (= 8 mod 16) after tfs).
//   k2_solver: FOUR lanes per pair. Lane r owns 4 plan rows (Kr[40]); row 0
//   replicated in all 4 lanes, counted x0.25 each (exact). Column reductions
//   close with 2-stage shfl_xor. Peak live ~100 regs -> 128-reg cap without
//   spills, 16 warps/SM.
// ---------------------------------------------------------------------------

#define N_NODES 10000
#define DIM 128
#define DEG 16
#define M_LOC 17
#define T_TPL 10
#define K_TPL 10
#define TK 100
#define N_PAIRS (N_NODES * T_TPL)
#define N_OUTER 5
#define N_SINK 10

__device__ float g_D[N_NODES * TK];   // dot(x[n], tf[t,k])
__device__ float g_xsq[N_NODES];
__device__ float g_gsq[TK];

// ---------------- Stage 1: dots + norms (register-tiled) ----------------
#define K1_NPB 32
#define K1_HALF 50
#define TF_STRIDE 129          // banks (tkl + e) % 32 -> conflict-free
#define X_STRIDE 36            // float4-aligned stride (36%4==0), [e][nl]

__global__ void __launch_bounds__(128) k1_dots(const float* __restrict__ x,
                                               const float* __restrict__ tf) {
    __shared__ alignas(16) float xst[DIM * X_STRIDE];    // 18.4 KB, xst[e*36 + nl]
    __shared__ alignas(16) float tfs[K1_HALF * TF_STRIDE]; // 25.8 KB
    const int tid = threadIdx.x;
    const int nbase = blockIdx.x * K1_NPB;

    // load x transposed: coalesced global, [e][nl] in smem
    for (int idx = tid; idx < K1_NPB * DIM; idx += 128) {
        int nl = idx >> 7, e = idx & 127;
        int n = nbase + nl;
        xst[e * X_STRIDE + nl] = (n < N_NODES) ? x[n * DIM + e] : 0.f;
    }

    const int tkl = (tid < 100) ? (tid % 50) : 0;
    const int qh  = (tid < 100) ? (tid / 50) : 0;   // node half: 16 nodes each

    #pragma unroll 1
    for (int s = 0; s < 2; s++) {
        __syncthreads();
        for (int idx = tid; idx < K1_HALF * DIM; idx += 128) {
            int tkr = idx >> 7, e = idx & 127;
            tfs[tkr * TF_STRIDE + e] = tf[(s * K1_HALF + tkr) * DIM + e];
        }
        __syncthreads();

        if (s == 0 && tid >= 100) {              // xsq on the 28 spare threads
            for (int nl = tid - 100; nl < K1_NPB; nl += 28) {
                int n = nbase + nl;
                if (n < N_NODES) {
                    float acc = 0.f;
                    #pragma unroll 8
                    for (int e = 0; e < DIM; e++) {
                        float c = xst[e * X_STRIDE + nl];
                        acc += c * c;
                    }
                    g_xsq[n] = acc;
                }
            }
        }
        if (blockIdx.x == 0 && tid < K1_HALF) {  // gsq
            float acc = 0.f;
            #pragma unroll 8
            for (int e = 0; e < DIM; e++) {
                float c = tfs[tid * TF_STRIDE + e];
                acc += c * c;
            }
            g_gsq[s * K1_HALF + tid] = acc;
        }
        if (tid < 100) {                          // main: 16 node-dots per thread
            float acc[16];
            #pragma unroll
            for (int i = 0; i < 16; i++) acc[i] = 0.f;
            const float* tfp = tfs + tkl * TF_STRIDE;
            const int nlo = qh * 16;
            #pragma unroll 4
            for (int e = 0; e < DIM; e++) {
                float tv = tfp[e];
                const float4* xp = (const float4*)(xst + e * X_STRIDE + nlo);
                float4 a0 = xp[0], a1 = xp[1], a2 = xp[2], a3 = xp[3];
                acc[0]  += tv * a0.x; acc[1]  += tv * a0.y; acc[2]  += tv * a0.z; acc[3]  += tv * a0.w;
                acc[4]  += tv * a1.x; acc[5]  += tv * a1.y; acc[6]  += tv * a1.z; acc[7]  += tv * a1.w;
                acc[8]  += tv * a2.x; acc[9]  += tv * a2.y; acc[10] += tv * a2.z; acc[11] += tv * a2.w;
                acc[12] += tv * a3.x; acc[13] += tv * a3.y; acc[14] += tv * a3.z; acc[15] += tv * a3.w;
            }
            int tk = s * K1_HALF + tkl;
            #pragma unroll
            for (int i = 0; i < 16; i++) {
                int n = nbase + nlo + i;
                if (n < N_NODES) g_D[n * TK + tk] = acc[i];
            }
        }
    }
}

// ---------------- Stage 2: FGW solver, 4 lanes per pair ----------------
#define BT 128                 // threads per block
#define PPB 32                 // pairs per block
#define ES_STRIDE 33           // banks 8r + pairlo -> 32 distinct, conflict-free

#define RED4(x) do { x += __shfl_xor_sync(0xffffffffu, x, 1); \
                     x += __shfl_xor_sync(0xffffffffu, x, 2); } while (0)

__global__ void __launch_bounds__(BT, 4) k2_solver(const int* __restrict__ edge_index,
                                                   const float* __restrict__ templates,
                                                   float* __restrict__ out) {
    __shared__ float Es[M_LOC * K_TPL * ES_STRIDE];   // 22440 B
    __shared__ float Cts[T_TPL * K_TPL * K_TPL];
    __shared__ float ctqs[TK];
    __shared__ float gsqs[TK];
    const int tid = threadIdx.x;
    const int r = tid & 3;                 // lane within pair
    const int pairlo = tid >> 2;           // pair index within block (0..31)
    const int pair = blockIdx.x * PPB + pairlo;

    for (int idx = tid; idx < T_TPL * K_TPL * K_TPL; idx += BT) Cts[idx] = templates[idx];
    for (int idx = tid; idx < TK; idx += BT) gsqs[idx] = g_gsq[idx];
    __syncthreads();
    for (int idx = tid; idx < TK; idx += BT) {
        int t = idx / K_TPL, j = idx - t * K_TPL;
        float s = 0.f;
        #pragma unroll
        for (int jp = 0; jp < K_TPL; jp++) { float c = Cts[t * 100 + j * 10 + jp]; s += c * c; }
        ctqs[idx] = s * 0.1f;
    }
    __syncthreads();
    if (pair >= N_PAIRS) return;           // grid exact (3125*32); warp-uniform regardless

    const int n = pair / T_TPL;
    const int t = pair - n * T_TPL;

    float* ep0 = Es + pairlo;                                 // row 0: j*33
    float* epo = Es + ((1 + 4 * r) * 10) * ES_STRIDE + pairlo; // own rows: (k*10+j)*33

    // ---- E = exp(-M): 4 own rows per lane; lane r==0 also fills row 0 ----
    {
        const float* gs = gsqs + t * K_TPL;
        #pragma unroll
        for (int k = 0; k < 4; k++) {
            int rr = edge_index[n * DEG + (4 * r + k)];
            float xsq = g_xsq[rr];
            const float* Dp = g_D + rr * TK + t * K_TPL;
            #pragma unroll
            for (int j = 0; j < 10; j++) {
                float Mij = (xsq + gs[j] - 2.f * Dp[j]) * (1.f / 128.f);
                epo[(k * 10 + j) * ES_STRIDE] = __expf(-Mij);
            }
        }
        if (r == 0) {
            float xsq = g_xsq[n];
            const float* Dp = g_D + n * TK + t * K_TPL;
            #pragma unroll
            for (int j = 0; j < 10; j++) {
                float Mij = (xsq + gs[j] - 2.f * Dp[j]) * (1.f / 128.f);
                ep0[j * ES_STRIDE] = __expf(-Mij);
            }
        }
    }
    __syncwarp();

    const float P   = 1.f / 17.f;
    const float P0c = 16.f / 17.f;
    const float Q   = 0.1f;
    const float* ct = Cts + t * 100;
    const float* cq = ctqs + t * K_TPL;

    float Kr0[10];                 // row 0, replicated in all 4 lanes
    float Kr[40];                  // 4 owned rows
    #pragma unroll
    for (int j = 0; j < 10; j++) Kr0[j] = 1.f / 170.f;
    #pragma unroll
    for (int ij = 0; ij < 40; ij++) Kr[ij] = 1.f / 170.f;

    float v[10];

    #pragma unroll 1
    for (int outer = 0; outer < N_OUTER; outer++) {
        // ---- a_j = colsum of rows 1..16 (own partial + 2-stage shfl) ----
        float a[10];
        #pragma unroll
        for (int j = 0; j < 10; j++) {
            float s = Kr[j] + Kr[10 + j] + Kr[20 + j] + Kr[30 + j];
            RED4(s);
            a[j] = s;
        }
        // ---- Gibbs weights ----
        float w[10], w0[10];
        #pragma unroll
        for (int j = 0; j < 10; j++) {
            float b = 0.f, G0 = 0.f;
            #pragma unroll
            for (int jp = 0; jp < 10; jp++) {
                float c = ct[j * 10 + jp];     // Ct symmetric
                b  += Kr0[jp] * c;
                G0 += a[jp] * c;
            }
            float c2 = cq[j];
            w[j]  = __expf(-2.f * (P   + c2 - 2.f * b));
            w0[j] = __expf(-2.f * (P0c + c2 - 2.f * G0));
        }
        // ---- Gibbs kernel: K = T * E * w ----
        #pragma unroll
        for (int j = 0; j < 10; j++) Kr0[j] *= ep0[j * ES_STRIDE] * w0[j];
        #pragma unroll
        for (int k = 0; k < 4; k++) {
            #pragma unroll
            for (int j = 0; j < 10; j++)
                Kr[k * 10 + j] *= epo[(k * 10 + j) * ES_STRIDE] * w[j];
        }
        // ---- Sinkhorn (primal), v starts at 1 ----
        #pragma unroll
        for (int j = 0; j < 10; j++) v[j] = 1.f;
        #pragma unroll 1
        for (int it = 0; it < N_SINK - 1; it++) {
            float s[10];
            float kv0 = 0.f;
            #pragma unroll
            for (int j = 0; j < 10; j++) kv0 += Kr0[j] * v[j];
            float u0q = 0.25f * __fdividef(P, kv0);        // quarter per lane
            #pragma unroll
            for (int j = 0; j < 10; j++) s[j] = Kr0[j] * u0q;
            #pragma unroll
            for (int k = 0; k < 4; k++) {
                float kv = 0.f;
                #pragma unroll
                for (int j = 0; j < 10; j++) kv += Kr[k * 10 + j] * v[j];
                float u = __fdividef(P, kv);
                #pragma unroll
                for (int j = 0; j < 10; j++) s[j] += Kr[k * 10 + j] * u;
            }
            #pragma unroll
            for (int j = 0; j < 10; j++) {
                float st = s[j];
                RED4(st);
                v[j] = __fdividef(Q, st);
            }
        }
        // ---- last Sinkhorn iter: keep u's, final v, fold T = K o u v^T ----
        {
            float s[10], uo[4];
            float kv0 = 0.f;
            #pragma unroll
            for (int j = 0; j < 10; j++) kv0 += Kr0[j] * v[j];
            float u0 = __fdividef(P, kv0);
            float u0q = 0.25f * u0;
            #pragma unroll
            for (int j = 0; j < 10; j++) s[j] = Kr0[j] * u0q;
            #pragma unroll
            for (int k = 0; k < 4; k++) {
                float kv = 0.f;
                #pragma unroll
                for (int j = 0; j < 10; j++) kv += Kr[k * 10 + j] * v[j];
                uo[k] = __fdividef(P, kv);
                #pragma unroll
                for (int j = 0; j < 10; j++) s[j] += Kr[k * 10 + j] * uo[k];
            }
            #pragma unroll
            for (int j = 0; j < 10; j++) {
                float st = s[j];
                RED4(st);
                v[j] = __fdividef(Q, st);
            }
            #pragma unroll
            for (int j = 0; j < 10; j++) Kr0[j] *= u0 * v[j];
            #pragma unroll
            for (int k = 0; k < 4; k++) {
                #pragma unroll
                for (int j = 0; j < 10; j++) Kr[k * 10 + j] *= uo[k] * v[j];
            }
        }
    }

    // ---- objective ----
    float a[10];
    #pragma unroll
    for (int j = 0; j < 10; j++) {
        float s = Kr[j] + Kr[10 + j] + Kr[20 + j] + Kr[30 + j];
        RED4(s);
        a[j] = s;
    }
    float obj = 0.f;
    #pragma unroll
    for (int j = 0; j < 10; j++) {
        float b = 0.f, G0 = 0.f;
        #pragma unroll
        for (int jp = 0; jp < 10; jp++) {
            float c = ct[j * 10 + jp];
            b  += Kr0[jp] * c;
            G0 += a[jp] * c;
        }
        float c2 = cq[j];
        float M0 = -__logf(ep0[j * ES_STRIDE]);
        // row 0 counted quarter per lane (identical values -> sums exactly)
        obj += 0.25f * Kr0[j] * (0.5f * M0 + 0.5f * (P0c + c2 - 2.f * G0));
        float cc = 0.5f * (P + c2 - 2.f * b);
        #pragma unroll
        for (int k = 0; k < 4; k++) {
            float Mij = -__logf(epo[(k * 10 + j) * ES_STRIDE]);
            obj += Kr[k * 10 + j] * (0.5f * Mij + cc);
        }
    }
    RED4(obj);
    if (r == 0) out[pair] = obj;
}

// ---------------- launch: kernel launches ONLY ----------------
extern "C" void kernel_launch(void* const* d_in, const int* in_sizes, int n_in,
                              void* d_out, int out_size) {
    const float* x    = (const float*)d_in[0];
    const int*   ei   = (const int*)d_in[1];     // row 0 = src
    const float* tmpl = (const float*)d_in[2];
    const float* tf   = (const float*)d_in[3];
    float* out = (float*)d_out;

    k1_dots<<<(N_NODES + K1_NPB - 1) / K1_NPB, 128>>>(x, tf);
    k2_solver<<<(N_PAIRS + PPB - 1) / PPB, BT>>>(ei, tmpl, out);
}

// round 11
// speedup vs baseline: 1.2822x; 1.2822x over previous
#include <cuda_runtime.h>

// ---------------------------------------------------------------------------
// LTFGW on GB300 (sm_103a). R10 = best measured components recombined:
//   k1_dots: register-tiled GEMM (R9, alignas(16) fix) — measured ~21us.
//   k2_solver: TWO lanes per pair, __launch_bounds__(128,3) (R6) — measured
//   239us. R9's 4-lane variant regressed (313us): still spilled at the
//   128-reg cap AND added ~1000 SHFLs/thread + 18% redundant row work.
// ---------------------------------------------------------------------------

#define N_NODES 10000
#define DIM 128
#define DEG 16
#define M_LOC 17
#define T_TPL 10
#define K_TPL 10
#define TK 100
#define N_PAIRS (N_NODES * T_TPL)
#define N_OUTER 5
#define N_SINK 10

__device__ float g_D[N_NODES * TK];   // dot(x[n], tf[t,k])
__device__ float g_xsq[N_NODES];
__device__ float g_gsq[TK];

// ---------------- Stage 1: dots + norms (register-tiled) ----------------
#define K1_NPB 32
#define K1_HALF 50
#define TF_STRIDE 129          // banks (tkl + e) % 32 -> conflict-free
#define X_STRIDE 36            // float4-aligned stride, [e][nl]

__global__ void __launch_bounds__(128) k1_dots(const float* __restrict__ x,
                                               const float* __restrict__ tf) {
    __shared__ alignas(16) float xst[DIM * X_STRIDE];      // 18.4 KB
    __shared__ alignas(16) float tfs[K1_HALF * TF_STRIDE]; // 25.8 KB
    const int tid = threadIdx.x;
    const int nbase = blockIdx.x * K1_NPB;

    for (int idx = tid; idx < K1_NPB * DIM; idx += 128) {
        int nl = idx >> 7, e = idx & 127;
        int n = nbase + nl;
        xst[e * X_STRIDE + nl] = (n < N_NODES) ? x[n * DIM + e] : 0.f;
    }

    const int tkl = (tid < 100) ? (tid % 50) : 0;
    const int qh  = (tid < 100) ? (tid / 50) : 0;

    #pragma unroll 1
    for (int s = 0; s < 2; s++) {
        __syncthreads();
        for (int idx = tid; idx < K1_HALF * DIM; idx += 128) {
            int tkr = idx >> 7, e = idx & 127;
            tfs[tkr * TF_STRIDE + e] = tf[(s * K1_HALF + tkr) * DIM + e];
        }
        __syncthreads();

        if (s == 0 && tid >= 100) {
            for (int nl = tid - 100; nl < K1_NPB; nl += 28) {
                int n = nbase + nl;
                if (n < N_NODES) {
                    float acc = 0.f;
                    #pragma unroll 8
                    for (int e = 0; e < DIM; e++) {
                        float c = xst[e * X_STRIDE + nl];
                        acc += c * c;
                    }
                    g_xsq[n] = acc;
                }
            }
        }
        if (blockIdx.x == 0 && tid < K1_HALF) {
            float acc = 0.f;
            #pragma unroll 8
            for (int e = 0; e < DIM; e++) {
                float c = tfs[tid * TF_STRIDE + e];
                acc += c * c;
            }
            g_gsq[s * K1_HALF + tid] = acc;
        }
        if (tid < 100) {
            float acc[16];
            #pragma unroll
            for (int i = 0; i < 16; i++) acc[i] = 0.f;
            const float* tfp = tfs + tkl * TF_STRIDE;
            const int nlo = qh * 16;
            #pragma unroll 4
            for (int e = 0; e < DIM; e++) {
                float tv = tfp[e];
                const float4* xp = (const float4*)(xst + e * X_STRIDE + nlo);
                float4 a0 = xp[0], a1 = xp[1], a2 = xp[2], a3 = xp[3];
                acc[0]  += tv * a0.x; acc[1]  += tv * a0.y; acc[2]  += tv * a0.z; acc[3]  += tv * a0.w;
                acc[4]  += tv * a1.x; acc[5]  += tv * a1.y; acc[6]  += tv * a1.z; acc[7]  += tv * a1.w;
                acc[8]  += tv * a2.x; acc[9]  += tv * a2.y; acc[10] += tv * a2.z; acc[11] += tv * a2.w;
                acc[12] += tv * a3.x; acc[13] += tv * a3.y; acc[14] += tv * a3.z; acc[15] += tv * a3.w;
            }
            int tk = s * K1_HALF + tkl;
            #pragma unroll
            for (int i = 0; i < 16; i++) {
                int n = nbase + nlo + i;
                if (n < N_NODES) g_D[n * TK + tk] = acc[i];
            }
        }
    }
}

// ---------------- Stage 2: FGW solver, 2 lanes per pair (R6 config) --------
#define BT 128                 // threads per block
#define PPB 64                 // pairs per block
#define ES_STRIDE 65           // bank-skewed stride for Es

__global__ void __launch_bounds__(BT, 3) k2_solver(const int* __restrict__ edge_index,
                                                   const float* __restrict__ templates,
                                                   float* __restrict__ out) {
    __shared__ float Es[M_LOC * K_TPL * ES_STRIDE];   // 44200 B
    __shared__ float Cts[T_TPL * K_TPL * K_TPL];
    __shared__ float ctqs[TK];
    __shared__ float gsqs[TK];
    const int tid = threadIdx.x;
    const int r = tid & 1;                 // lane parity within pair
    const int pairlo = tid >> 1;           // pair index within block (0..63)
    const int pair = blockIdx.x * PPB + pairlo;

    for (int idx = tid; idx < T_TPL * K_TPL * K_TPL; idx += BT) Cts[idx] = templates[idx];
    for (int idx = tid; idx < TK; idx += BT) gsqs[idx] = g_gsq[idx];
    __syncthreads();
    for (int idx = tid; idx < TK; idx += BT) {
        int t = idx / K_TPL, j = idx - t * K_TPL;
        float s = 0.f;
        #pragma unroll
        for (int jp = 0; jp < K_TPL; jp++) { float c = Cts[t * 100 + j * 10 + jp]; s += c * c; }
        ctqs[idx] = s * 0.1f;
    }
    __syncthreads();
    if (pair >= N_PAIRS) return;

    const int n = pair / T_TPL;
    const int t = pair - n * T_TPL;
    const int base = 1 + 8 * r;            // first owned row: 1 or 9

    float* ep0 = Es + pairlo;                              // row 0, index j*65
    float* epo = Es + (base * 10) * ES_STRIDE + pairlo;    // own rows, (k*10+j)*65

    // ---- E = exp(-M) fill: 8 own rows per lane; lane0 also fills row 0 ----
    {
        const float* gs = gsqs + t * K_TPL;
        #pragma unroll
        for (int k = 0; k < 8; k++) {
            int rr = edge_index[n * DEG + (base - 1 + k)];
            float xsq = g_xsq[rr];
            const float* Dp = g_D + rr * TK + t * K_TPL;
            #pragma unroll
            for (int j = 0; j < 10; j++) {
                float Mij = (xsq + gs[j] - 2.f * Dp[j]) * (1.f / 128.f);
                epo[(k * 10 + j) * ES_STRIDE] = __expf(-Mij);
            }
        }
        if (r == 0) {
            float xsq = g_xsq[n];
            const float* Dp = g_D + n * TK + t * K_TPL;
            #pragma unroll
            for (int j = 0; j < 10; j++) {
                float Mij = (xsq + gs[j] - 2.f * Dp[j]) * (1.f / 128.f);
                ep0[j * ES_STRIDE] = __expf(-Mij);
            }
        }
    }
    __syncwarp();

    const float P   = 1.f / 17.f;
    const float P0c = 16.f / 17.f;
    const float Q   = 0.1f;
    const float* ct = Cts + t * 100;
    const float* cq = ctqs + t * K_TPL;

    float Kr0[10];                 // row 0 of plan, replicated both lanes
    float Kr[80];                  // 8 owned rows
    #pragma unroll
    for (int j = 0; j < 10; j++) Kr0[j] = 1.f / 170.f;
    #pragma unroll
    for (int ij = 0; ij < 80; ij++) Kr[ij] = 1.f / 170.f;

    float v[10];

    #pragma unroll 1
    for (int outer = 0; outer < N_OUTER; outer++) {
        // ---- a_j = colsum of rows 1..16 (own partial + partner via shfl) ----
        float a[10];
        #pragma unroll
        for (int j = 0; j < 10; j++) {
            float s = 0.f;
            #pragma unroll
            for (int k = 0; k < 8; k++) s += Kr[k * 10 + j];
            a[j] = s + __shfl_xor_sync(0xffffffffu, s, 1);
        }
        // ---- Gibbs weights ----
        float w[10], w0[10];
        #pragma unroll
        for (int j = 0; j < 10; j++) {
            float b = 0.f, G0 = 0.f;
            #pragma unroll
            for (int jp = 0; jp < 10; jp++) {
                float c = ct[j * 10 + jp];     // Ct symmetric
                b  += Kr0[jp] * c;
                G0 += a[jp] * c;
            }
            float c2 = cq[j];
            w[j]  = __expf(-2.f * (P   + c2 - 2.f * b));
            w0[j] = __expf(-2.f * (P0c + c2 - 2.f * G0));
        }
        // ---- Gibbs kernel: K = T * E * w ----
        #pragma unroll
        for (int j = 0; j < 10; j++) Kr0[j] *= ep0[j * ES_STRIDE] * w0[j];
        #pragma unroll
        for (int k = 0; k < 8; k++) {
            #pragma unroll
            for (int j = 0; j < 10; j++)
                Kr[k * 10 + j] *= epo[(k * 10 + j) * ES_STRIDE] * w[j];
        }
        // ---- Sinkhorn (primal), v starts at 1 ----
        #pragma unroll
        for (int j = 0; j < 10; j++) v[j] = 1.f;
        #pragma unroll 1
        for (int it = 0; it < N_SINK - 1; it++) {
            float s[10];
            float kv0 = 0.f;
            #pragma unroll
            for (int j = 0; j < 10; j++) kv0 += Kr0[j] * v[j];
            float u0h = 0.5f * __fdividef(P, kv0);          // half per lane
            #pragma unroll
            for (int j = 0; j < 10; j++) s[j] = Kr0[j] * u0h;
            #pragma unroll
            for (int k = 0; k < 8; k++) {
                float kv = 0.f;
                #pragma unroll
                for (int j = 0; j < 10; j++) kv += Kr[k * 10 + j] * v[j];
                float u = __fdividef(P, kv);
                #pragma unroll
                for (int j = 0; j < 10; j++) s[j] += Kr[k * 10 + j] * u;
            }
            #pragma unroll
            for (int j = 0; j < 10; j++) {
                float st = s[j] + __shfl_xor_sync(0xffffffffu, s[j], 1);
                v[j] = __fdividef(Q, st);
            }
        }
        // ---- last Sinkhorn iter: keep u's, final v, fold T = K o u v^T ----
        {
            float s[10], uo[8];
            float kv0 = 0.f;
            #pragma unroll
            for (int j = 0; j < 10; j++) kv0 += Kr0[j] * v[j];
            float u0 = __fdividef(P, kv0);
            float u0h = 0.5f * u0;
            #pragma unroll
            for (int j = 0; j < 10; j++) s[j] = Kr0[j] * u0h;
            #pragma unroll
            for (int k = 0; k < 8; k++) {
                float kv = 0.f;
                #pragma unroll
                for (int j = 0; j < 10; j++) kv += Kr[k * 10 + j] * v[j];
                uo[k] = __fdividef(P, kv);
                #pragma unroll
                for (int j = 0; j < 10; j++) s[j] += Kr[k * 10 + j] * uo[k];
            }
            #pragma unroll
            for (int j = 0; j < 10; j++) {
                float st = s[j] + __shfl_xor_sync(0xffffffffu, s[j], 1);
                v[j] = __fdividef(Q, st);
            }
            #pragma unroll
            for (int j = 0; j < 10; j++) Kr0[j] *= u0 * v[j];
            #pragma unroll
            for (int k = 0; k < 8; k++) {
                #pragma unroll
                for (int j = 0; j < 10; j++) Kr[k * 10 + j] *= uo[k] * v[j];
            }
        }
    }

    // ---- objective ----
    float a[10];
    #pragma unroll
    for (int j = 0; j < 10; j++) {
        float s = 0.f;
        #pragma unroll
        for (int k = 0; k < 8; k++) s += Kr[k * 10 + j];
        a[j] = s + __shfl_xor_sync(0xffffffffu, s, 1);
    }
    float obj = 0.f;
    #pragma unroll
    for (int j = 0; j < 10; j++) {
        float b = 0.f, G0 = 0.f;
        #pragma unroll
        for (int jp = 0; jp < 10; jp++) {
            float c = ct[j * 10 + jp];
            b  += Kr0[jp] * c;
            G0 += a[jp] * c;
        }
        float c2 = cq[j];
        float M0 = -__logf(ep0[j * ES_STRIDE]);
        obj += 0.5f * Kr0[j] * (0.5f * M0 + 0.5f * (P0c + c2 - 2.f * G0));
        float cc = 0.5f * (P + c2 - 2.f * b);
        #pragma unroll
        for (int k = 0; k < 8; k++) {
            float Mij = -__logf(epo[(k * 10 + j) * ES_STRIDE]);
            obj += Kr[k * 10 + j] * (0.5f * Mij + cc);
        }
    }
    obj += __shfl_xor_sync(0xffffffffu, obj, 1);
    if (r == 0) out[pair] = obj;
}

// ---------------- launch: kernel launches ONLY ----------------
extern "C" void kernel_launch(void* const* d_in, const int* in_sizes, int n_in,
                              void* d_out, int out_size) {
    const float* x    = (const float*)d_in[0];
    const int*   ei   = (const int*)d_in[1];     // row 0 = src
    const float* tmpl = (const float*)d_in[2];
    const float* tf   = (const float*)d_in[3];
    float* out = (float*)d_out;

    k1_dots<<<(N_NODES + K1_NPB - 1) / K1_NPB, 128>>>(x, tf);
    k2_solver<<<(N_PAIRS + PPB - 1) / PPB, BT>>>(ei, tmpl, out);
}